// round 1
// baseline (speedup 1.0000x reference)
#include <cuda_runtime.h>

// LengthRegulatorWithDurations: expand encoder_out[B,T,D] by durations[B,T]
// into out[B,MAX_LEN,D], plus mel_lens[B] appended (as float) at the tail.
//
// B=16, T=512, D=384, MAX_LEN=4096. Output f32: 16*4096*384 (+16 tail).

#define NB 16
#define NT 512
#define ND 384
#define MAXL 4096
#define NVEC (ND / 4)        // 96 float4 per row
#define ROWS_PER_BLK 32
#define SUBS 4               // 384 threads / 96 lanes

__device__ int g_cum[NB * NT];

// --- Kernel A: per-batch inclusive scan of durations; stash cum + mel_lens ---
__global__ void lr_scan_kernel(const int* __restrict__ dur,
                               float* __restrict__ out_tail /* may be null */) {
    __shared__ int s[NT];
    const int b = blockIdx.x;
    const int t = threadIdx.x;
    s[t] = dur[b * NT + t];
    __syncthreads();
    // Hillis-Steele inclusive scan over 512 elements (9 steps)
    #pragma unroll
    for (int off = 1; off < NT; off <<= 1) {
        int x = (t >= off) ? s[t - off] : 0;
        __syncthreads();
        s[t] += x;
        __syncthreads();
    }
    g_cum[b * NT + t] = s[t];
    if (t == NT - 1 && out_tail != nullptr) {
        out_tail[b] = (float)s[t];   // mel_lens as f32 in the flattened output
    }
}

// --- Kernel B: expand. grid = (MAXL/ROWS_PER_BLK, B), block = 384 threads. ---
// Warp layout: threads 0..95 handle row sub-slot 0, 96..191 slot 1, etc.
// Each warp therefore has a uniform mel position p -> the binary search over
// the smem cum array is broadcast (no divergence, no bank conflicts).
__global__ void lr_expand_kernel(const float4* __restrict__ enc,
                                 float4* __restrict__ out) {
    __shared__ int cum[NT];
    const int b = blockIdx.y;
    // stage this batch's cumulative durations into smem
    for (int i = threadIdx.x; i < NT; i += blockDim.x)
        cum[i] = g_cum[b * NT + i];
    __syncthreads();

    const int mel_len = cum[NT - 1];           // valid iff p < min(mel_len, MAXL)
    const int lane = threadIdx.x % NVEC;       // 0..95  (float4 index within row)
    const int sub  = threadIdx.x / NVEC;       // 0..3
    const int row0 = blockIdx.x * ROWS_PER_BLK;

    #pragma unroll
    for (int r = sub; r < ROWS_PER_BLK; r += SUBS) {
        const int p = row0 + r;                // mel position, < MAXL by construction
        float4 val = make_float4(0.f, 0.f, 0.f, 0.f);
        if (p < mel_len) {
            // searchsorted(cum, p, side='right'): first idx with cum[idx] > p
            int lo = 0, hi = NT;
            #pragma unroll
            while (lo < hi) {
                int mid = (lo + hi) >> 1;
                if (cum[mid] <= p) lo = mid + 1; else hi = mid;
            }
            int tok = min(lo, NT - 1);
            val = enc[((size_t)b * NT + tok) * NVEC + lane];
        }
        out[((size_t)b * MAXL + p) * NVEC + lane] = val;
    }
}

extern "C" void kernel_launch(void* const* d_in, const int* in_sizes, int n_in,
                              void* d_out, int out_size) {
    const float* enc = (const float*)d_in[0];
    const int*   dur = (const int*)d_in[1];
    float* out = (float*)d_out;

    const long long expanded_elems = (long long)NB * MAXL * ND;
    float* tail = ((long long)out_size >= expanded_elems + NB)
                      ? (out + expanded_elems) : nullptr;

    lr_scan_kernel<<<NB, NT>>>(dur, tail);

    dim3 grid(MAXL / ROWS_PER_BLK, NB);
    lr_expand_kernel<<<grid, NVEC * SUBS>>>((const float4*)enc, (float4*)out);
}

// round 10
// speedup vs baseline: 1.3361x; 1.3361x over previous
#include <cuda_runtime.h>

// LengthRegulatorWithDurations, fused single kernel.
// expand encoder_out[B,T,D] by durations[B,T] into out[B,MAX_LEN,D],
// plus mel_lens[B] (as float) at the tail.
// B=16, T=512, D=384, MAX_LEN=4096.
//
// Each block: (1) recompute the inclusive scan of durations[b,:] in smem
// (cheap: 2KB read + ~30 ALU ops), (2) one warp-group computes the 32 row->token
// indices via binary search, (3) 384 threads copy 32 rows with batched
// MLP=8 float4 loads and fully-coalesced float4 stores.

#define NB 16
#define NT 512
#define ND 384
#define MAXL 4096
#define NVEC (ND / 4)        // 96 float4 per row
#define ROWS_PER_BLK 32
#define SUBS 4               // 384 threads / 96 lanes
#define RPT (ROWS_PER_BLK / SUBS)   // 8 rows per thread
#define NTHREADS (NVEC * SUBS)      // 384

__global__ void __launch_bounds__(NTHREADS)
lr_fused_kernel(const float4* __restrict__ enc,
                const int* __restrict__ dur,
                float4* __restrict__ out,
                float* __restrict__ out_tail /* may be null */) {
    __shared__ int cum[NT];
    __shared__ int wsums[4];             // 4 scan warps
    __shared__ int toks[ROWS_PER_BLK];   // -1 => invalid (zero-fill)

    const int b = blockIdx.y;
    const int tid = threadIdx.x;
    const int row0 = blockIdx.x * ROWS_PER_BLK;

    // ---- Phase 1: inclusive scan of durations[b, 0..511] into smem cum ----
    // Threads 0..127: 4 consecutive elements each.
    int s0 = 0, s1 = 0, s2 = 0, s3 = 0;
    if (tid < 128) {
        const int base = b * NT + tid * 4;
        const int d0 = dur[base + 0];
        const int d1 = dur[base + 1];
        const int d2 = dur[base + 2];
        const int d3 = dur[base + 3];
        s0 = d0; s1 = s0 + d1; s2 = s1 + d2; s3 = s2 + d3;
        // inclusive warp scan over per-thread totals (s3)
        int tot = s3;
        const int lane = tid & 31;
        #pragma unroll
        for (int o = 1; o < 32; o <<= 1) {
            int x = __shfl_up_sync(0xffffffffu, tot, o);
            if (lane >= o) tot += x;
        }
        if (lane == 31) wsums[tid >> 5] = tot;
        // exclusive prefix within warp for this thread's 4 elements
        const int thr_prefix = tot - s3;
        s0 += thr_prefix; s1 += thr_prefix; s2 += thr_prefix; s3 += thr_prefix;
    }
    __syncthreads();
    if (tid < 128) {
        const int w = tid >> 5;
        int wp = 0;
        #pragma unroll
        for (int i = 0; i < 4; i++)
            if (i < w) wp += wsums[i];
        const int base = tid * 4;
        cum[base + 0] = s0 + wp;
        cum[base + 1] = s1 + wp;
        cum[base + 2] = s2 + wp;
        cum[base + 3] = s3 + wp;
    }
    __syncthreads();

    const int mel_len = cum[NT - 1];
    if (out_tail != nullptr && blockIdx.x == 0 && tid == 0)
        out_tail[b] = (float)mel_len;    // mel_lens as f32

    // ---- Phase 2: one search per row (threads 0..31), broadcast via smem ----
    if (tid < ROWS_PER_BLK) {
        const int p = row0 + tid;
        int tok = -1;
        if (p < mel_len) {
            // searchsorted(cum, p, 'right'): first idx with cum[idx] > p
            int lo = 0, hi = NT;
            #pragma unroll
            while (lo < hi) {
                int mid = (lo + hi) >> 1;
                if (cum[mid] <= p) lo = mid + 1; else hi = mid;
            }
            tok = min(lo, NT - 1);
        }
        toks[tid] = tok;
    }
    __syncthreads();

    // ---- Phase 3: copy. 96 lanes * float4 = one coalesced 1536B row. ----
    const int lane = tid % NVEC;         // float4 index within row
    const int sub  = tid / NVEC;         // 0..3

    const float4* encb = enc + (size_t)b * NT * NVEC + lane;
    float4* outb = out + ((size_t)b * MAXL + row0 + sub) * NVEC + lane;

    int tk[RPT];
    #pragma unroll
    for (int i = 0; i < RPT; i++)
        tk[i] = toks[sub + i * SUBS];

    float4 v[RPT];
    #pragma unroll
    for (int i = 0; i < RPT; i++) {
        v[i] = make_float4(0.f, 0.f, 0.f, 0.f);
        if (tk[i] >= 0)
            v[i] = encb[(size_t)tk[i] * NVEC];
    }
    #pragma unroll
    for (int i = 0; i < RPT; i++)
        outb[(size_t)i * SUBS * NVEC] = v[i];
}

extern "C" void kernel_launch(void* const* d_in, const int* in_sizes, int n_in,
                              void* d_out, int out_size) {
    const float* enc = (const float*)d_in[0];
    const int*   dur = (const int*)d_in[1];
    float* out = (float*)d_out;

    const long long expanded_elems = (long long)NB * MAXL * ND;
    float* tail = ((long long)out_size >= expanded_elems + NB)
                      ? (out + expanded_elems) : nullptr;

    dim3 grid(MAXL / ROWS_PER_BLK, NB);
    lr_fused_kernel<<<grid, NTHREADS>>>((const float4*)enc, dur,
                                        (float4*)out, tail);
}